// round 6
// baseline (speedup 1.0000x reference)
#include <cuda_runtime.h>
#include <cuda_fp16.h>
#include <cstdint>

// Problem constants
#define B_   2
#define S_   2048
#define E_   1024
#define H_   16
#define D_   64
#define HD_  1024
#define N_   4096            // B*S
#define SCALE_ 0.125f        // 1/sqrt(64), exact power of two
#define NEG_  -1e9f

// ---------------- scratch (device globals; no allocations allowed) -------
__device__ __half g_qh[(size_t)B_ * H_ * S_ * D_];   // [bh][s][d], pre-scaled
__device__ __half g_kh[(size_t)B_ * H_ * S_ * D_];
__device__ __half g_vh[(size_t)B_ * H_ * S_ * D_];
__device__ __half g_ctxh[(size_t)N_ * HD_];          // [b*S+s][h*D+d]
__device__ __half g_ah[(size_t)N_ * E_];             // staged A (fp16)
__device__ __half g_wth[(size_t)E_ * HD_];           // staged W^T (fp16) [n][k]
__device__ int    g_mask_mode;                       // 0=u8, 1=i32, 2=f32

// ---------------- helpers --------------------------------------------------
__device__ __forceinline__ uint32_t cvta_smem(const void* p) {
    uint32_t a;
    asm("{ .reg .u64 t; cvta.to.shared.u64 t, %1; cvt.u32.u64 %0, t; }"
        : "=r"(a) : "l"(p));
    return a;
}
__device__ __forceinline__ void ldmx4(uint32_t* d, uint32_t a) {
    asm volatile("ldmatrix.sync.aligned.m8n8.x4.shared.b16 {%0,%1,%2,%3}, [%4];"
                 : "=r"(d[0]), "=r"(d[1]), "=r"(d[2]), "=r"(d[3]) : "r"(a));
}
__device__ __forceinline__ void ldmx4t(uint32_t* d, uint32_t a) {
    asm volatile("ldmatrix.sync.aligned.m8n8.x4.trans.shared.b16 {%0,%1,%2,%3}, [%4];"
                 : "=r"(d[0]), "=r"(d[1]), "=r"(d[2]), "=r"(d[3]) : "r"(a));
}
__device__ __forceinline__ void mma_f16(float* c, const uint32_t* a,
                                        const uint32_t* b) {
    asm volatile(
        "mma.sync.aligned.m16n8k16.row.col.f32.f16.f16.f32 "
        "{%0,%1,%2,%3}, {%4,%5,%6,%7}, {%8,%9}, {%0,%1,%2,%3};"
        : "+f"(c[0]), "+f"(c[1]), "+f"(c[2]), "+f"(c[3])
        : "r"(a[0]), "r"(a[1]), "r"(a[2]), "r"(a[3]), "r"(b[0]), "r"(b[1]));
}

// ---------------- staging kernels ------------------------------------------
// fp32 -> fp16 elementwise (A operands). grid 4096 x 256 thr, 4 elem/thr.
__global__ void conv_a_kernel(const float* __restrict__ in,
                              __half* __restrict__ out) {
    size_t i = ((size_t)blockIdx.x * 256 + threadIdx.x) * 4;
    float4 v = *(const float4*)(in + i);
    __half2 h0 = __floats2half2_rn(v.x, v.y);
    __half2 h1 = __floats2half2_rn(v.z, v.w);
    *(__half2*)(out + i)     = h0;
    *(__half2*)(out + i + 2) = h1;
}

// W[k][n] fp32 -> WT[n][k] fp16, 32x32 smem tile transpose. grid (32,32),(32,8)
__global__ void conv_wt_kernel(const float* __restrict__ W,
                               __half* __restrict__ WT) {
    __shared__ __half t[32][33];
    int n0 = blockIdx.x * 32, k0 = blockIdx.y * 32;
    int tx = threadIdx.x, ty = threadIdx.y;
#pragma unroll
    for (int i = 0; i < 4; i++)
        t[ty + i * 8][tx] = __float2half(W[(size_t)(k0 + ty + i * 8) * HD_ + n0 + tx]);
    __syncthreads();
#pragma unroll
    for (int i = 0; i < 4; i++)
        WT[(size_t)(n0 + ty + i * 8) * E_ + k0 + tx] = t[tx][ty + i * 8];
}

// ---------------- mask dtype detector --------------------------------------
__global__ void detect_mask_kernel(const unsigned int* __restrict__ m) {
    unsigned int v = m[threadIdx.x];
    int isf = (v == 0x3F800000u);
    int big = (v > 1u);
    isf = __syncthreads_or(isf);
    big = __syncthreads_or(big);
    if (threadIdx.x == 0) g_mask_mode = isf ? 2 : (big ? 0 : 1);
}

// ============ fp16 ldmatrix GEMM: out = A[4096,1024]@W[1024,1024]+bias ======
// A, W^T staged fp16. CTA tile 128x128, 8 warps (2m x 4n), warp 64x32,
// K chunks of 32 (2 kt), double-buffered row-major smem, 16B XOR swizzle
// (4 chunks/row, c ^= row&3). Frags via ldmatrix.
__global__ void __launch_bounds__(256) gemm_h_kernel(
    const __half* __restrict__ Ah, const __half* __restrict__ WT,
    const float* __restrict__ bias, float* __restrict__ outp, int sel) {

    __shared__ __half sA[2][128 * 32];
    __shared__ __half sB[2][128 * 32];

    const int tid = threadIdx.x;
    const int wid = tid >> 5, lane = tid & 31;
    const int m0 = blockIdx.y * 128, c0 = blockIdx.x * 128;
    const int warpM = wid & 1, warpN = wid >> 1;
    const int g = lane >> 2, tq = lane & 3;

    const uint32_t sAb0 = cvta_smem(sA[0]), sBb0 = cvta_smem(sB[0]);

    // loader: 2 x 16B chunks per operand per thread
    const int l_row = tid >> 2;            // 0..63 base rows (x2 sets)
    const int l_c   = tid & 3;             // chunk 0..3
    // two rows per thread: l_row and l_row+64
    float* dummy;
    (void)dummy;

    uint4 aregs[2], bregs[2];
    auto ldg_chunk = [&](int k0) {
#pragma unroll
        for (int e = 0; e < 2; e++) {
            int row = l_row + e * 64;
            aregs[e] = *(const uint4*)(Ah + (size_t)(m0 + row) * E_ + k0 + l_c * 8);
            bregs[e] = *(const uint4*)(WT + (size_t)(c0 + row) * E_ + k0 + l_c * 8);
        }
    };
    auto sts_chunk = [&](int buf) {
#pragma unroll
        for (int e = 0; e < 2; e++) {
            int row = l_row + e * 64;
            int cs = (l_c ^ (row & 3)) * 8;
            *(uint4*)(sA[buf] + row * 32 + cs) = aregs[e];
            *(uint4*)(sB[buf] + row * 32 + cs) = bregs[e];
        }
    };

    // ldmatrix lane geometry (fixed per thread)
    const int lr8 = (lane & 7) + ((lane >> 3) & 1) * 8;  // row within 16
    const int ls4 = lane >> 4;                           // chunk sel 0/1
    // A: 4 i tiles, rows warpM*64 + i*16 + lr8
    int a_rr[4], b_rr[2];
#pragma unroll
    for (int i = 0; i < 4; i++) a_rr[i] = warpM * 64 + i * 16 + lr8;
#pragma unroll
    for (int j = 0; j < 2; j++) b_rr[j] = warpN * 32 + j * 16 + lr8;

    float c[4][4][4] = {};

    ldg_chunk(0);
    sts_chunk(0);
    __syncthreads();

    for (int ch = 0; ch < 32; ch++) {
        const int buf = ch & 1;
        if (ch < 31) ldg_chunk((ch + 1) * 32);

        const uint32_t ab = sAb0 + buf * (128 * 32 * 2);
        const uint32_t bb = sBb0 + buf * (128 * 32 * 2);
#pragma unroll
        for (int kt = 0; kt < 2; kt++) {
            uint32_t af[4][4];
            uint32_t bf[4][2];
#pragma unroll
            for (int i = 0; i < 4; i++) {
                int cc = ((kt << 1) | ls4) ^ (a_rr[i] & 3);
                ldmx4(af[i], ab + a_rr[i] * 64 + cc * 16);
            }
#pragma unroll
            for (int jj = 0; jj < 2; jj++) {
                int cc = ((kt << 1) | ls4) ^ (b_rr[jj] & 3);
                uint32_t t4[4];
                ldmx4(t4, bb + b_rr[jj] * 64 + cc * 16);
                bf[jj * 2][0] = t4[0]; bf[jj * 2 + 1][0] = t4[1];
                bf[jj * 2][1] = t4[2]; bf[jj * 2 + 1][1] = t4[3];
            }
#pragma unroll
            for (int i = 0; i < 4; i++)
#pragma unroll
                for (int j = 0; j < 4; j++)
                    mma_f16(c[i][j], af[i], bf[j]);
        }

        if (ch < 31) sts_chunk(buf ^ 1);
        __syncthreads();
    }

    // ---- epilogue -----------------------------------------------------------
    const float osc = (sel == 0) ? SCALE_ : 1.0f;
    __half* hdst = (sel == 0) ? g_qh : (sel == 1) ? g_kh : g_vh;
#pragma unroll
    for (int i = 0; i < 4; i++) {
        int rtop = m0 + warpM * 64 + i * 16 + g;
        int rbot = rtop + 8;
#pragma unroll
        for (int j = 0; j < 4; j++) {
            int coln = c0 + warpN * 32 + j * 8 + tq * 2;
            float2 bb2 = *(const float2*)(bias + coln);
            float v00 = c[i][j][0] + bb2.x, v01 = c[i][j][1] + bb2.y;
            float v10 = c[i][j][2] + bb2.x, v11 = c[i][j][3] + bb2.y;
            if (sel < 3) {
                int hI = coln >> 6, dI = coln & 63;
                int b0I = rtop >> 11, s0I = rtop & (S_ - 1);
                int b1I = rbot >> 11, s1I = rbot & (S_ - 1);
                *(__half2*)(hdst + (((size_t)b0I * H_ + hI) * S_ + s0I) * D_ + dI) =
                    __floats2half2_rn(v00 * osc, v01 * osc);
                *(__half2*)(hdst + (((size_t)b1I * H_ + hI) * S_ + s1I) * D_ + dI) =
                    __floats2half2_rn(v10 * osc, v11 * osc);
            } else {
                *(float2*)(outp + (size_t)rtop * HD_ + coln) = make_float2(v00, v01);
                *(float2*)(outp + (size_t)rbot * HD_ + coln) = make_float2(v10, v11);
            }
        }
    }
}

// ---------------- attention: recompute-in-pass-2, fp16 ldmatrix mma --------
// grid (S/64, B*H), 256 thr = 8 warps (2m x 4n).
// Pass 1: per 64-k tile: K->smem, mma scores -> sS, scalar mask + online (m,l).
//         NO global score traffic.
// Pass 2: recompute scores (K L2-resident), p=exp(s-m)/l -> prob HBM + hP smem,
//         mma ctx += P @ V.
#define ATTN_SMEM (4 * 8192 + 64 * 68 * 4)

__global__ void __launch_bounds__(256) attn_kernel(
    const void* __restrict__ mask, float* __restrict__ prob) {

    extern __shared__ char smraw[];
    __half* hQ = (__half*)smraw;            // 64x64
    __half* hK = hQ + 4096;
    __half* hV = hK + 4096;
    __half* hP = hV + 4096;
    float*  sS = (float*)(smraw + 32768);   // 64x68

    const int tid = threadIdx.x, tx = tid & 15, ty = tid >> 4;
    const int wid = tid >> 5, lane = tid & 31;
    const int warpM = wid & 1, warpN = wid >> 1;
    const int g = lane >> 2, tq = lane & 3;
    const int bh = blockIdx.y, q0 = blockIdx.x * 64;
    const int bI = bh >> 4, hI = bh & 15;

    const __half* qg = g_qh + (size_t)bh * S_ * D_ + (size_t)q0 * D_;
    const __half* kg = g_kh + (size_t)bh * S_ * D_;
    const __half* vg = g_vh + (size_t)bh * S_ * D_;
    float* sc = prob + ((size_t)bh * S_ + q0) * S_;
    const int mm = g_mask_mode;

    const uint32_t hQb = cvta_smem(hQ), hKb = cvta_smem(hK);
    const uint32_t hVb = cvta_smem(hV), hPb = cvta_smem(hP);

    // tile loader: 64x64 halves, 8 chunks/row, swizzle c^(row&7)
    const int tl_row = tid >> 2;      // x2 sets of 64 rows? 64 rows total:
    // 512 chunks / 256 thr = 2 chunks/thr: rows tid>>2 (0..63), chunks (tid&3)*2, +1
    auto load_tile = [&](__half* dst, const __half* src, int k0) {
#pragma unroll
        for (int e = 0; e < 2; e++) {
            int row = tl_row;
            int c = (tid & 3) * 2 + e;
            uint4 v = *(const uint4*)(src + (size_t)(k0 + row) * 64 + c * 8);
            *(uint4*)(dst + row * 64 + ((c ^ (row & 7)) * 8)) = v;
        }
    };

    // ldmatrix lane geometry
    const int lr8 = (lane & 7) + ((lane >> 3) & 1) * 8;
    const int ls4 = lane >> 4;
    int q_rr[2];
#pragma unroll
    for (int i = 0; i < 2; i++) q_rr[i] = warpM * 32 + i * 16 + lr8;
    const int k_rr = warpN * 16 + lr8;
    const int v_cc_raw = warpN * 2 + ls4;     // V trans: chunk = d block

    // mma scores into cs
    auto mma_scores = [&](float cs[2][2][4], uint32_t qb) {
#pragma unroll
        for (int i = 0; i < 2; i++)
#pragma unroll
            for (int j = 0; j < 2; j++)
#pragma unroll
                for (int r = 0; r < 4; r++) cs[i][j][r] = 0.f;
#pragma unroll
        for (int kt = 0; kt < 4; kt++) {
            uint32_t af[2][4], bf[2][2], t4[4];
#pragma unroll
            for (int i = 0; i < 2; i++) {
                int cc = ((kt << 1) | ls4) ^ (q_rr[i] & 7);
                ldmx4(af[i], qb + q_rr[i] * 128 + cc * 16);
            }
            {
                int cc = ((kt << 1) | ls4) ^ (k_rr & 7);
                ldmx4(t4, hKb + k_rr * 128 + cc * 16);
                bf[0][0] = t4[0]; bf[1][0] = t4[1];
                bf[0][1] = t4[2]; bf[1][1] = t4[3];
            }
#pragma unroll
            for (int i = 0; i < 2; i++)
#pragma unroll
                for (int j = 0; j < 2; j++)
                    mma_f16(cs[i][j], af[i], bf[j]);
        }
    };
    auto dump_scores = [&](float cs[2][2][4]) {
#pragma unroll
        for (int i = 0; i < 2; i++) {
            int r0 = warpM * 32 + i * 16 + g;
#pragma unroll
            for (int j = 0; j < 2; j++) {
                int cl = warpN * 16 + j * 8 + tq * 2;
                *(float2*)(sS + r0 * 68 + cl)       = make_float2(cs[i][j][0], cs[i][j][1]);
                *(float2*)(sS + (r0 + 8) * 68 + cl) = make_float2(cs[i][j][2], cs[i][j][3]);
            }
        }
    };

    // ---- load Q tile (pre-scaled fp16) -----------------------------------
    load_tile(hQ, qg - 0, 0);   // qg already offset by q0; k0=0 over its 64 rows
    __syncthreads();

    float m[4] = {-1e30f, -1e30f, -1e30f, -1e30f};
    float l[4] = {0.f, 0.f, 0.f, 0.f};

    // =================== pass 1: online (m,l) only ========================
    for (int kt0 = 0; kt0 < 32; kt0++) {
        const int k0 = kt0 * 64;
        load_tile(hK, kg, k0);
        __syncthreads();
        float cs[2][2][4];
        mma_scores(cs, hQb);
        dump_scores(cs);
        __syncthreads();

#pragma unroll
        for (int ir = 0; ir < 4; ir++) {
            int row = ty * 4 + ir;
            float4 s4 = *(const float4*)(sS + row * 68 + tx * 4);
            float acc[4] = {s4.x, s4.y, s4.z, s4.w};
            size_t moff = ((size_t)bI * S_ + q0 + row) * S_ + k0 + tx * 4;
            if (mm == 0) {
                uchar4 u = *(const uchar4*)((const unsigned char*)mask + moff);
                if (u.x) acc[0] = NEG_;
                if (u.y) acc[1] = NEG_;
                if (u.z) acc[2] = NEG_;
                if (u.w) acc[3] = NEG_;
            } else if (mm == 1) {
                int4 u = *(const int4*)((const int*)mask + moff);
                if (u.x) acc[0] = NEG_;
                if (u.y) acc[1] = NEG_;
                if (u.z) acc[2] = NEG_;
                if (u.w) acc[3] = NEG_;
            } else {
                float4 u = *(const float4*)((const float*)mask + moff);
                if (u.x != 0.f) acc[0] = NEG_;
                if (u.y != 0.f) acc[1] = NEG_;
                if (u.z != 0.f) acc[2] = NEG_;
                if (u.w != 0.f) acc[3] = NEG_;
            }
            float tm = fmaxf(fmaxf(acc[0], acc[1]), fmaxf(acc[2], acc[3]));
#pragma unroll
            for (int o = 8; o; o >>= 1)
                tm = fmaxf(tm, __shfl_xor_sync(0xffffffffu, tm, o));
            float mn = fmaxf(m[ir], tm);
            float ps = __expf(acc[0] - mn) + __expf(acc[1] - mn)
                     + __expf(acc[2] - mn) + __expf(acc[3] - mn);
#pragma unroll
            for (int o = 8; o; o >>= 1)
                ps += __shfl_xor_sync(0xffffffffu, ps, o);
            l[ir] = l[ir] * __expf(m[ir] - mn) + ps;
            m[ir] = mn;
        }
        __syncthreads();
    }

    // =================== pass 2: prob + ctx = P @ V =======================
    float il[4];
#pragma unroll
    for (int ir = 0; ir < 4; ir++) il[ir] = 1.0f / l[ir];
    float ctx[2][2][4] = {};

    for (int kt0 = 0; kt0 < 32; kt0++) {
        const int k0 = kt0 * 64;
        load_tile(hK, kg, k0);
        load_tile(hV, vg, k0);
        __syncthreads();
        float cs[2][2][4];
        mma_scores(cs, hQb);
        dump_scores(cs);
        __syncthreads();

#pragma unroll
        for (int ir = 0; ir < 4; ir++) {
            int row = ty * 4 + ir;
            float4 s4 = *(const float4*)(sS + row * 68 + tx * 4);
            float acc[4] = {s4.x, s4.y, s4.z, s4.w};
            size_t moff = ((size_t)bI * S_ + q0 + row) * S_ + k0 + tx * 4;
            if (mm == 0) {
                uchar4 u = *(const uchar4*)((const unsigned char*)mask + moff);
                if (u.x) acc[0] = NEG_;
                if (u.y) acc[1] = NEG_;
                if (u.z) acc[2] = NEG_;
                if (u.w) acc[3] = NEG_;
            } else if (mm == 1) {
                int4 u = *(const int4*)((const int*)mask + moff);
                if (u.x) acc[0] = NEG_;
                if (u.y) acc[1] = NEG_;
                if (u.z) acc[2] = NEG_;
                if (u.w) acc[3] = NEG_;
            } else {
                float4 u = *(const float4*)((const float*)mask + moff);
                if (u.x != 0.f) acc[0] = NEG_;
                if (u.y != 0.f) acc[1] = NEG_;
                if (u.z != 0.f) acc[2] = NEG_;
                if (u.w != 0.f) acc[3] = NEG_;
            }
            float4 p4;
            p4.x = __expf(acc[0] - m[ir]) * il[ir];
            p4.y = __expf(acc[1] - m[ir]) * il[ir];
            p4.z = __expf(acc[2] - m[ir]) * il[ir];
            p4.w = __expf(acc[3] - m[ir]) * il[ir];
            *(float4*)(sc + (size_t)row * S_ + k0 + tx * 4) = p4;   // prob out
            // P into swizzled fp16 smem
            int c = tx >> 1;
            __half* pp = hP + row * 64 + ((c ^ (row & 7)) * 8) + (tx & 1) * 4;
            *(__half2*)(pp)     = __floats2half2_rn(p4.x, p4.y);
            *(__half2*)(pp + 2) = __floats2half2_rn(p4.z, p4.w);
        }
        __syncthreads();

        // ctx += P(64x64) @ V(64x64)
#pragma unroll
        for (int kt = 0; kt < 4; kt++) {
            uint32_t pf[2][4], vf[2][2], t4[4];
#pragma unroll
            for (int i = 0; i < 2; i++) {
                int cc = ((kt << 1) | ls4) ^ (q_rr[i] & 7);
                ldmx4(pf[i], hPb + q_rr[i] * 128 + cc * 16);
            }
            {
                int rr = kt * 16 + lr8;
                int cc = v_cc_raw ^ (rr & 7);
                ldmx4t(t4, hVb + rr * 128 + cc * 16);
                vf[0][0] = t4[0]; vf[0][1] = t4[1];
                vf[1][0] = t4[2]; vf[1][1] = t4[3];
            }
#pragma unroll
            for (int i = 0; i < 2; i++)
#pragma unroll
                for (int j = 0; j < 2; j++)
                    mma_f16(ctx[i][j], pf[i], vf[j]);
        }
        __syncthreads();
    }

    // ---- store ctx (fp16) -------------------------------------------------
#pragma unroll
    for (int i = 0; i < 2; i++) {
        int r0 = q0 + warpM * 32 + i * 16 + g;
#pragma unroll
        for (int j = 0; j < 2; j++) {
            int cl = hI * 64 + warpN * 16 + j * 8 + tq * 2;
            *(__half2*)(g_ctxh + ((size_t)bI * S_ + r0) * HD_ + cl) =
                __floats2half2_rn(ctx[i][j][0], ctx[i][j][1]);
            *(__half2*)(g_ctxh + ((size_t)bI * S_ + r0 + 8) * HD_ + cl) =
                __floats2half2_rn(ctx[i][j][2], ctx[i][j][3]);
        }
    }
}

// ---------------- launcher ------------------------------------------------
extern "C" void kernel_launch(void* const* d_in, const int* in_sizes, int n_in,
                              void* d_out, int out_size) {
    const float* Q  = (const float*)d_in[0];
    const float* K  = (const float*)d_in[1];
    const float* V  = (const float*)d_in[2];
    const void*  mask = d_in[3];
    const float* WQ = (const float*)d_in[4];
    const float* bQ = (const float*)d_in[5];
    const float* WK = (const float*)d_in[6];
    const float* bK = (const float*)d_in[7];
    const float* WV = (const float*)d_in[8];
    const float* bV = (const float*)d_in[9];
    const float* WO = (const float*)d_in[10];
    const float* bO = (const float*)d_in[11];

    float* y    = (float*)d_out;
    float* prob = y + (size_t)N_ * E_;

    __half *ah, *wth, *ctxh;
    cudaGetSymbolAddress((void**)&ah,   g_ah);
    cudaGetSymbolAddress((void**)&wth,  g_wth);
    cudaGetSymbolAddress((void**)&ctxh, g_ctxh);

    cudaFuncSetAttribute(attn_kernel,
                         cudaFuncAttributeMaxDynamicSharedMemorySize, ATTN_SMEM);

    dim3 blk(256);
    dim3 gproj(HD_ / 128, N_ / 128);
    dim3 gwt(32, 32);
    dim3 bwt(32, 8);

    conv_wt_kernel<<<gwt, bwt>>>(WQ, wth);
    conv_a_kernel<<<4096, 256>>>(Q, ah);
    gemm_h_kernel<<<gproj, blk>>>(ah, wth, bQ, nullptr, 0);

    conv_wt_kernel<<<gwt, bwt>>>(WK, wth);
    conv_a_kernel<<<4096, 256>>>(K, ah);
    gemm_h_kernel<<<gproj, blk>>>(ah, wth, bK, nullptr, 1);

    conv_wt_kernel<<<gwt, bwt>>>(WV, wth);
    conv_a_kernel<<<4096, 256>>>(V, ah);
    gemm_h_kernel<<<gproj, blk>>>(ah, wth, bV, nullptr, 2);

    detect_mask_kernel<<<1, 256>>>((const unsigned int*)mask);
    attn_kernel<<<dim3(S_ / 64, B_ * H_), blk, ATTN_SMEM>>>(mask, prob);

    conv_wt_kernel<<<gwt, bwt>>>(WO, wth);
    gemm_h_kernel<<<gproj, blk>>>(ctxh, wth, bO, y, 3);
}